// round 16
// baseline (speedup 1.0000x reference)
#include <cuda_runtime.h>
#include <math_constants.h>

// Until: out[b,t,x] = min(phi[b,t,x], max(psi[b,t,x], out[b,t-1,x])), out[-1] = -1e6.
// Single-pass chained scan (decoupled lookback). Monoid f(v)=min(A,max(B,v)):
//   compose (later∘earlier): A' = min(A2, max(B2, A1)), B' = max(B1, B2).
// R16: decentralized tail — every warp redundantly combines the lookback window
// (all warps own all 32 x-lanes), one barrier per round via double-buffered
// window smem, and a barrier-FREE post-lookback (per-warp carries, __syncwarp
// only). TC=512: 1024 blocks = single resident wave, chain depth 16.

#define B_   64
#define T_   8192
#define X_   32
#define TC_  512                // time steps per chunk
#define C_   (T_ / TC_)         // 16 chunks per batch
#define NB_  (B_ * C_)          // 1024 blocks (single wave at 8 CTA/SM)
#define SL_  32                 // t-slices per block
#define PT_  (TC_ / SL_)        // 16 steps per thread
#define NW_  8                  // warps per block == lookback window size
#define SPW_ (SL_ / NW_)        // 4 slices per warp
#define LARGE_ 1.0e6f

typedef unsigned long long u64;

// one 16B record per (chunk, x): {pk(tag, A_or_P), pk(tag, B)}
__device__ ulonglong2 g_ABpk[NB_ * X_];
__device__ int g_ticket;          // never reset; epoch = ticket / NB_

__device__ __forceinline__ u64 pk(int tag, float v) {
    return ((u64)(unsigned)tag << 32) | (u64)__float_as_uint(v);
}

__device__ __forceinline__ void st_v2_vol(ulonglong2* p, u64 a, u64 b) {
    asm volatile("st.volatile.global.v2.u64 [%0], {%1, %2};"
                 :: "l"(p), "l"(a), "l"(b) : "memory");
}

__device__ __forceinline__ ulonglong2 ld_v2_vol(const ulonglong2* p) {
    ulonglong2 r;
    asm volatile("ld.volatile.global.v2.u64 {%0, %1}, [%2];"
                 : "=l"(r.x), "=l"(r.y) : "l"(p) : "memory");
    return r;
}

__global__ void __launch_bounds__(256, 8) until_scan(const float* __restrict__ phi,
                                                     const float* __restrict__ psi,
                                                     float* __restrict__ out) {
    __shared__ float sA[SL_][X_];       // per-slice aggregate A
    __shared__ float sB[SL_][X_];       // per-slice aggregate B
    __shared__ float sWA[NW_][X_];      // per-warp fold of its 4 slices
    __shared__ float sWB[NW_][X_];
    __shared__ float sGC[NW_][X_];      // carry entering each warp's slice group
    __shared__ float wLA[2][NW_][X_];   // double-buffered window payload (A or P)
    __shared__ float wLB[2][NW_][X_];   // window payload (B)
    __shared__ int   wSt[2][NW_][X_];   // per-lane status: 1 = PRE, 0 = AGG
    __shared__ float sFA[X_];           // block aggregate A
    __shared__ float sFB[X_];           // block aggregate B
    __shared__ int   s_tic;

    const int tid = threadIdx.x;
    if (tid == 0) s_tic = atomicAdd(&g_ticket, 1);
    __syncthreads();
    const int traw = s_tic;
    const int e    = traw >> 10;          // epoch (NB_ = 1024)
    const int v    = traw & (NB_ - 1);
    const int b    = v % B_;              // breadth-first over chunks
    const int c    = v / B_;              // 0..15
    const int bc   = b * C_ + c;
    const int FLAG_AGG = 2 * e + 1;
    const int FLAG_PRE = 2 * e + 2;

    const int xg   = tid & 7;             // float4 group along x
    const int xq   = xg * 4;
    const int s    = tid >> 3;            // slice 0..31
    const int w    = tid >> 5;            // warp 0..7
    const int lane = tid & 31;

    // 32-bit element indexing off one base
    const unsigned fbase = (unsigned)(b * (T_ * X_ / 4) + (c * TC_ + s * PT_) * (X_ / 4) + xg);
    const float4* pp = (const float4*)phi + fbase;
    const float4* qq = (const float4*)psi + fbase;

    // ---------- phase 1: streaming slice aggregate (lines land in L2) ----------
    float4 A  = make_float4( CUDART_INF_F,  CUDART_INF_F,  CUDART_INF_F,  CUDART_INF_F);
    float4 Bc = make_float4(-CUDART_INF_F, -CUDART_INF_F, -CUDART_INF_F, -CUDART_INF_F);
#pragma unroll
    for (int i = 0; i < PT_; i++) {
        float4 p = pp[i * (X_ / 4)];
        float4 q = qq[i * (X_ / 4)];
        A.x = fminf(p.x, fmaxf(q.x, A.x));  Bc.x = fmaxf(q.x, Bc.x);
        A.y = fminf(p.y, fmaxf(q.y, A.y));  Bc.y = fmaxf(q.y, Bc.y);
        A.z = fminf(p.z, fmaxf(q.z, A.z));  Bc.z = fmaxf(q.z, Bc.z);
        A.w = fminf(p.w, fmaxf(q.w, A.w));  Bc.w = fmaxf(q.w, Bc.w);
    }
    sA[s][xq + 0] = A.x;  sA[s][xq + 1] = A.y;  sA[s][xq + 2] = A.z;  sA[s][xq + 3] = A.w;
    sB[s][xq + 0] = Bc.x; sB[s][xq + 1] = Bc.y; sB[s][xq + 2] = Bc.z; sB[s][xq + 3] = Bc.w;
    __syncwarp();   // slices 4w..4w+3 are written by warp w's own threads

    // ---------- fold level 1: warp w folds its 4 slices (lane = x) ----------
    {
        float wA =  CUDART_INF_F;
        float wB = -CUDART_INF_F;
#pragma unroll
        for (int j = 0; j < SPW_; j++) {
            const int sl = w * SPW_ + j;
            wA = fminf(sA[sl][lane], fmaxf(sB[sl][lane], wA));
            wB = fmaxf(sB[sl][lane], wB);
        }
        sWA[w][lane] = wA;
        sWB[w][lane] = wB;
    }
    __syncthreads();

    // ---------- warp 0: fold level 2 + publish AGG (one 16B store) ----------
    if (tid < 32) {
        const int x = tid;
        float Ab =  CUDART_INF_F;
        float Bb = -CUDART_INF_F;
#pragma unroll
        for (int j = 0; j < NW_; j++) {
            Ab = fminf(sWA[j][x], fmaxf(sWB[j][x], Ab));
            Bb = fmaxf(sWB[j][x], Bb);
        }
        sFA[x] = Ab;
        sFB[x] = Bb;
        // chunk 0 never publishes AGG -> lookback can't cross batch boundary
        if (c > 0) {
            st_v2_vol(&g_ABpk[bc * X_ + x], pk(FLAG_AGG, Ab), pk(FLAG_AGG, Bb));
        }
    }
    __syncthreads();   // sFA/sFB + sWA/sWB visible to all warps

    // ---------- lookback: 8 probes/round, EVERY warp combines redundantly ----------
    float vin = -LARGE_;                  // per-lane x = lane, valid in ALL warps
    if (c > 0) {
        const int batch_lo = b * C_;      // chunk 0 of this batch (always reaches PRE)
        int hi  = bc - 1;
        int par = 0;
        float accA =  CUDART_INF_F;
        float accB = -CUDART_INF_F;
        int found = 0;
        while (true) {
            // probe: warp w reads predecessor hi-w (per-lane x = lane)
            const int j = hi - w;
            if (j >= batch_lo) {
                const ulonglong2* gp = &g_ABpk[j * X_ + lane];
                int st; float av, bv;
                while (true) {
                    ulonglong2 r = ld_v2_vol(gp);
                    const int t0 = (int)(r.x >> 32);
                    if (t0 == FLAG_PRE) {                 // resolved prefix
                        st = 1; av = __uint_as_float((unsigned)r.x); bv = -CUDART_INF_F;
                        break;
                    }
                    if (t0 == FLAG_AGG && (int)(r.y >> 32) == FLAG_AGG) {
                        st = 0; av = __uint_as_float((unsigned)r.x);
                        bv = __uint_as_float((unsigned)r.y);
                        break;
                    }
                    // not published yet, or torn AGG->PRE overwrite: retry
                }
                wLA[par][w][lane] = av;
                wLB[par][w][lane] = bv;
                wSt[par][w][lane] = st;
            }
            __syncthreads();              // the ONLY barrier in the round

            // combine: every warp, identical computation on its own lanes
            if (!found) {
#pragma unroll
                for (int k = 0; k < NW_; k++) {
                    if (hi - k < batch_lo) break;         // below batch floor
                    if (wSt[par][k][lane]) {              // PRE: resolve this lane
                        vin = fminf(accA, fmaxf(accB, wLA[par][k][lane]));
                        found = 1;
                        break;
                    }
                    accA = fminf(accA, fmaxf(accB, wLA[par][k][lane]));
                    accB = fmaxf(accB, wLB[par][k][lane]);
                }
            }
            // uniform across warps (identical data -> identical result)
            if (__all_sync(0xffffffffu, found)) break;
            hi -= NW_;
            par ^= 1;                     // next probe writes the other buffer
        }
    }

    // ---------- barrier-free tail: per-warp PRE publish + group carry ----------
    if (w == 0) {
        // publish inclusive prefix ASAP (lane = x)
        float pre = fminf(sFA[lane], fmaxf(sFB[lane], vin));
        st_v2_vol(&g_ABpk[bc * X_ + lane], pk(FLAG_PRE, pre), pk(FLAG_PRE, 0.0f));
    }
    {
        // warp w: carry entering its slice group = vin pushed through groups 0..w-1
        float gc = vin;
        for (int j = 0; j < w; j++)
            gc = fminf(sWA[j][lane], fmaxf(sWB[j][lane], gc));
        sGC[w][lane] = gc;
    }
    __syncwarp();                         // only warp w's threads read sGC[w]

    // ---------- per-thread slice carry (walk <=3 slices from warp-group carry) ----------
    float v0 = sGC[w][xq + 0];
    float v1 = sGC[w][xq + 1];
    float v2 = sGC[w][xq + 2];
    float v3 = sGC[w][xq + 3];
    for (int j = w * SPW_; j < s; j++) {
        v0 = fminf(sA[j][xq + 0], fmaxf(sB[j][xq + 0], v0));
        v1 = fminf(sA[j][xq + 1], fmaxf(sB[j][xq + 1], v1));
        v2 = fminf(sA[j][xq + 2], fmaxf(sB[j][xq + 2], v2));
        v3 = fminf(sA[j][xq + 3], fmaxf(sB[j][xq + 3], v3));
    }
    float4 vc = make_float4(v0, v1, v2, v3);

    // ---------- phase 2: reload (L2 hits), apply carry, stream out ----------
    float4* oo = (float4*)out + fbase;
#pragma unroll
    for (int i = 0; i < PT_; i++) {
        float4 p = __ldcs(&pp[i * (X_ / 4)]);
        float4 q = __ldcs(&qq[i * (X_ / 4)]);
        vc.x = fminf(p.x, fmaxf(q.x, vc.x));
        vc.y = fminf(p.y, fmaxf(q.y, vc.y));
        vc.z = fminf(p.z, fmaxf(q.z, vc.z));
        vc.w = fminf(p.w, fmaxf(q.w, vc.w));
        __stcs(&oo[i * (X_ / 4)], vc);
    }
}

extern "C" void kernel_launch(void* const* d_in, const int* in_sizes, int n_in,
                              void* d_out, int out_size) {
    const float* phi = (const float*)d_in[0];
    const float* psi = (const float*)d_in[1];
    float* out = (float*)d_out;

    until_scan<<<NB_, 256>>>(phi, psi, out);
}

// round 17
// speedup vs baseline: 1.1234x; 1.1234x over previous
#include <cuda_runtime.h>
#include <math_constants.h>

// Until: out[b,t,x] = min(phi[b,t,x], max(psi[b,t,x], out[b,t-1,x])), out[-1] = -1e6.
// Single-pass chained scan (decoupled lookback). Monoid f(v)=min(A,max(B,v)):
//   compose (later∘earlier): A' = min(A2, max(B2, A1)), B' = max(B1, B2).
// R17: R16's decentralized one-barrier lookback + barrier-free tail, with
// TC=256 restored so phase-2 reloads stay L2-resident (R16's TC=512 pushed the
// in-flight working set past L2 and re-read ~50MB from DRAM).

#define B_   64
#define T_   8192
#define X_   32
#define TC_  256                // time steps per chunk
#define C_   (T_ / TC_)         // 32 chunks per batch
#define NB_  (B_ * C_)          // 2048 blocks (~2 waves at 8 CTA/SM)
#define SL_  32                 // t-slices per block
#define PT_  (TC_ / SL_)        // 8 steps per thread
#define NW_  8                  // warps per block == lookback window size
#define SPW_ (SL_ / NW_)        // 4 slices per warp
#define LARGE_ 1.0e6f

typedef unsigned long long u64;

// one 16B record per (chunk, x): {pk(tag, A_or_P), pk(tag, B)}
__device__ ulonglong2 g_ABpk[NB_ * X_];
__device__ int g_ticket;          // never reset; epoch = ticket / NB_

__device__ __forceinline__ u64 pk(int tag, float v) {
    return ((u64)(unsigned)tag << 32) | (u64)__float_as_uint(v);
}

__device__ __forceinline__ void st_v2_vol(ulonglong2* p, u64 a, u64 b) {
    asm volatile("st.volatile.global.v2.u64 [%0], {%1, %2};"
                 :: "l"(p), "l"(a), "l"(b) : "memory");
}

__device__ __forceinline__ ulonglong2 ld_v2_vol(const ulonglong2* p) {
    ulonglong2 r;
    asm volatile("ld.volatile.global.v2.u64 {%0, %1}, [%2];"
                 : "=l"(r.x), "=l"(r.y) : "l"(p) : "memory");
    return r;
}

__global__ void __launch_bounds__(256, 8) until_scan(const float* __restrict__ phi,
                                                     const float* __restrict__ psi,
                                                     float* __restrict__ out) {
    __shared__ float sA[SL_][X_];       // per-slice aggregate A
    __shared__ float sB[SL_][X_];       // per-slice aggregate B
    __shared__ float sWA[NW_][X_];      // per-warp fold of its 4 slices
    __shared__ float sWB[NW_][X_];
    __shared__ float sGC[NW_][X_];      // carry entering each warp's slice group
    __shared__ float wLA[2][NW_][X_];   // double-buffered window payload (A or P)
    __shared__ float wLB[2][NW_][X_];   // window payload (B)
    __shared__ int   wSt[2][NW_][X_];   // per-lane status: 1 = PRE, 0 = AGG
    __shared__ float sFA[X_];           // block aggregate A
    __shared__ float sFB[X_];           // block aggregate B
    __shared__ int   s_tic;

    const int tid = threadIdx.x;
    if (tid == 0) s_tic = atomicAdd(&g_ticket, 1);
    __syncthreads();
    const int traw = s_tic;
    const int e    = traw >> 11;          // epoch (NB_ = 2048)
    const int v    = traw & (NB_ - 1);
    const int b    = v % B_;              // breadth-first over chunks
    const int c    = v / B_;              // 0..31
    const int bc   = b * C_ + c;
    const int FLAG_AGG = 2 * e + 1;
    const int FLAG_PRE = 2 * e + 2;

    const int xg   = tid & 7;             // float4 group along x
    const int xq   = xg * 4;
    const int s    = tid >> 3;            // slice 0..31
    const int w    = tid >> 5;            // warp 0..7
    const int lane = tid & 31;

    // 32-bit element indexing off one base
    const unsigned fbase = (unsigned)(b * (T_ * X_ / 4) + (c * TC_ + s * PT_) * (X_ / 4) + xg);
    const float4* pp = (const float4*)phi + fbase;
    const float4* qq = (const float4*)psi + fbase;

    // ---------- phase 1: streaming slice aggregate (lines land in L2) ----------
    float4 A  = make_float4( CUDART_INF_F,  CUDART_INF_F,  CUDART_INF_F,  CUDART_INF_F);
    float4 Bc = make_float4(-CUDART_INF_F, -CUDART_INF_F, -CUDART_INF_F, -CUDART_INF_F);
#pragma unroll
    for (int i = 0; i < PT_; i++) {
        float4 p = pp[i * (X_ / 4)];
        float4 q = qq[i * (X_ / 4)];
        A.x = fminf(p.x, fmaxf(q.x, A.x));  Bc.x = fmaxf(q.x, Bc.x);
        A.y = fminf(p.y, fmaxf(q.y, A.y));  Bc.y = fmaxf(q.y, Bc.y);
        A.z = fminf(p.z, fmaxf(q.z, A.z));  Bc.z = fmaxf(q.z, Bc.z);
        A.w = fminf(p.w, fmaxf(q.w, A.w));  Bc.w = fmaxf(q.w, Bc.w);
    }
    sA[s][xq + 0] = A.x;  sA[s][xq + 1] = A.y;  sA[s][xq + 2] = A.z;  sA[s][xq + 3] = A.w;
    sB[s][xq + 0] = Bc.x; sB[s][xq + 1] = Bc.y; sB[s][xq + 2] = Bc.z; sB[s][xq + 3] = Bc.w;
    __syncwarp();   // slices 4w..4w+3 are written by warp w's own threads

    // ---------- fold level 1: warp w folds its 4 slices (lane = x) ----------
    {
        float wA =  CUDART_INF_F;
        float wB = -CUDART_INF_F;
#pragma unroll
        for (int j = 0; j < SPW_; j++) {
            const int sl = w * SPW_ + j;
            wA = fminf(sA[sl][lane], fmaxf(sB[sl][lane], wA));
            wB = fmaxf(sB[sl][lane], wB);
        }
        sWA[w][lane] = wA;
        sWB[w][lane] = wB;
    }
    __syncthreads();

    // ---------- warp 0: fold level 2 + publish AGG (one 16B store) ----------
    if (tid < 32) {
        const int x = tid;
        float Ab =  CUDART_INF_F;
        float Bb = -CUDART_INF_F;
#pragma unroll
        for (int j = 0; j < NW_; j++) {
            Ab = fminf(sWA[j][x], fmaxf(sWB[j][x], Ab));
            Bb = fmaxf(sWB[j][x], Bb);
        }
        sFA[x] = Ab;
        sFB[x] = Bb;
        // chunk 0 never publishes AGG -> lookback can't cross batch boundary
        if (c > 0) {
            st_v2_vol(&g_ABpk[bc * X_ + x], pk(FLAG_AGG, Ab), pk(FLAG_AGG, Bb));
        }
    }
    __syncthreads();   // sFA/sFB + sWA/sWB visible to all warps

    // ---------- lookback: 8 probes/round, EVERY warp combines redundantly ----------
    float vin = -LARGE_;                  // per-lane x = lane, valid in ALL warps
    if (c > 0) {
        const int batch_lo = b * C_;      // chunk 0 of this batch (always reaches PRE)
        int hi  = bc - 1;
        int par = 0;
        float accA =  CUDART_INF_F;
        float accB = -CUDART_INF_F;
        int found = 0;
        while (true) {
            // probe: warp w reads predecessor hi-w (per-lane x = lane)
            const int j = hi - w;
            if (j >= batch_lo) {
                const ulonglong2* gp = &g_ABpk[j * X_ + lane];
                int st; float av, bv;
                while (true) {
                    ulonglong2 r = ld_v2_vol(gp);
                    const int t0 = (int)(r.x >> 32);
                    if (t0 == FLAG_PRE) {                 // resolved prefix
                        st = 1; av = __uint_as_float((unsigned)r.x); bv = -CUDART_INF_F;
                        break;
                    }
                    if (t0 == FLAG_AGG && (int)(r.y >> 32) == FLAG_AGG) {
                        st = 0; av = __uint_as_float((unsigned)r.x);
                        bv = __uint_as_float((unsigned)r.y);
                        break;
                    }
                    // not published yet, or torn AGG->PRE overwrite: retry
                }
                wLA[par][w][lane] = av;
                wLB[par][w][lane] = bv;
                wSt[par][w][lane] = st;
            }
            __syncthreads();              // the ONLY barrier in the round

            // combine: every warp, identical computation on its own lanes
            if (!found) {
#pragma unroll
                for (int k = 0; k < NW_; k++) {
                    if (hi - k < batch_lo) break;         // below batch floor
                    if (wSt[par][k][lane]) {              // PRE: resolve this lane
                        vin = fminf(accA, fmaxf(accB, wLA[par][k][lane]));
                        found = 1;
                        break;
                    }
                    accA = fminf(accA, fmaxf(accB, wLA[par][k][lane]));
                    accB = fmaxf(accB, wLB[par][k][lane]);
                }
            }
            // uniform across warps (identical data -> identical result)
            if (__all_sync(0xffffffffu, found)) break;
            hi -= NW_;
            par ^= 1;                     // next probe writes the other buffer
        }
    }

    // ---------- barrier-free tail: per-warp PRE publish + group carry ----------
    if (w == 0) {
        // publish inclusive prefix ASAP (lane = x)
        float pre = fminf(sFA[lane], fmaxf(sFB[lane], vin));
        st_v2_vol(&g_ABpk[bc * X_ + lane], pk(FLAG_PRE, pre), pk(FLAG_PRE, 0.0f));
    }
    {
        // warp w: carry entering its slice group = vin pushed through groups 0..w-1
        float gc = vin;
        for (int j = 0; j < w; j++)
            gc = fminf(sWA[j][lane], fmaxf(sWB[j][lane], gc));
        sGC[w][lane] = gc;
    }
    __syncwarp();                         // only warp w's threads read sGC[w]

    // ---------- per-thread slice carry (walk <=3 slices from warp-group carry) ----------
    float v0 = sGC[w][xq + 0];
    float v1 = sGC[w][xq + 1];
    float v2 = sGC[w][xq + 2];
    float v3 = sGC[w][xq + 3];
    for (int j = w * SPW_; j < s; j++) {
        v0 = fminf(sA[j][xq + 0], fmaxf(sB[j][xq + 0], v0));
        v1 = fminf(sA[j][xq + 1], fmaxf(sB[j][xq + 1], v1));
        v2 = fminf(sA[j][xq + 2], fmaxf(sB[j][xq + 2], v2));
        v3 = fminf(sA[j][xq + 3], fmaxf(sB[j][xq + 3], v3));
    }
    float4 vc = make_float4(v0, v1, v2, v3);

    // ---------- phase 2: reload (L2 hits), apply carry, stream out ----------
    float4* oo = (float4*)out + fbase;
#pragma unroll
    for (int i = 0; i < PT_; i++) {
        float4 p = __ldcs(&pp[i * (X_ / 4)]);
        float4 q = __ldcs(&qq[i * (X_ / 4)]);
        vc.x = fminf(p.x, fmaxf(q.x, vc.x));
        vc.y = fminf(p.y, fmaxf(q.y, vc.y));
        vc.z = fminf(p.z, fmaxf(q.z, vc.z));
        vc.w = fminf(p.w, fmaxf(q.w, vc.w));
        __stcs(&oo[i * (X_ / 4)], vc);
    }
}

extern "C" void kernel_launch(void* const* d_in, const int* in_sizes, int n_in,
                              void* d_out, int out_size) {
    const float* phi = (const float*)d_in[0];
    const float* psi = (const float*)d_in[1];
    float* out = (float*)d_out;

    until_scan<<<NB_, 256>>>(phi, psi, out);
}